// round 15
// baseline (speedup 1.0000x reference)
#include <cuda_runtime.h>
#include <cuda_fp16.h>
#include <cstdint>

#define D_MODEL 1024
#define NHEAD   16
#define DK      64
#define BB      2
#define SEQ     2048
#define MROWS   (BB * SEQ)   // 4096
#define NBH     (BB * NHEAD) // 32

// attention tiling
#define QROWS 64
#define CHUNK 128
#define NCH   (SEQ / CHUNK)  // 16

// attention smem strides in HALVES
#define QSTRH 72
#define KSTRH 72
#define VSTRH 72
#define KBUFB (128 * KSTRH * 2)   // 18432 B
#define VBUFB (128 * VSTRH * 2)   // 18432 B

// fp16 GEMM strides (halves) / pipeline
#define ASTRH 40                  // A tile [128 m][32 k]
#define BSTRH 136                 // B tile [32 k][128 n]
#define NST   3
#define ATILEH (128 * ASTRH)      // 5120 halves
#define BTILEH (32 * BSTRH)       // 4352 halves

// ---------------- scratch (device globals) -----------------------------------
__device__ __half g_qin[MROWS * D_MODEL];
__device__ __half g_kin[MROWS * D_MODEL];
__device__ __half g_vin[MROWS * D_MODEL];
__device__ __half g_wqc[D_MODEL * D_MODEL];
__device__ __half g_wkc[D_MODEL * D_MODEL];
__device__ __half g_wvc[D_MODEL * D_MODEL];
__device__ __half g_woc[D_MODEL * D_MODEL];
__device__ __half g_qh [NBH * SEQ * DK];   // [bh][s][d] fp16, pre-scaled 1/8
__device__ __half g_kh [NBH * SEQ * DK];   // [bh][s][d] fp16
__device__ __half g_vh [NBH * SEQ * DK];   // [bh][s][d] fp16
__device__ __half g_ctx[MROWS * D_MODEL];  // [b*S+s][h*64+d] fp16
__device__ __half g_us [(size_t)NBH * SEQ * SEQ];  // unnormalized u (fp16), 268MB

// ---------------- helpers ----------------------------------------------------
__device__ __forceinline__ uint32_t pack2h(float a, float b) {
    __half2 h = __floats2half2_rn(a, b);
    return *(uint32_t*)&h;
}

// fp16 m16n8k16
__device__ __forceinline__ void mmah(float* d, const uint32_t* a,
                                     uint32_t b0, uint32_t b1) {
    asm volatile(
        "mma.sync.aligned.m16n8k16.row.col.f32.f16.f16.f32 "
        "{%0,%1,%2,%3}, {%4,%5,%6,%7}, {%8,%9}, {%0,%1,%2,%3};"
        : "+f"(d[0]), "+f"(d[1]), "+f"(d[2]), "+f"(d[3])
        : "r"(a[0]), "r"(a[1]), "r"(a[2]), "r"(a[3]), "r"(b0), "r"(b1));
}

__device__ __forceinline__ void ldsm4(uint32_t* r, uint32_t saddr) {
    asm volatile(
        "ldmatrix.sync.aligned.m8n8.x4.shared.b16 {%0,%1,%2,%3}, [%4];"
        : "=r"(r[0]), "=r"(r[1]), "=r"(r[2]), "=r"(r[3]) : "r"(saddr));
}

__device__ __forceinline__ void ldsm4t(uint32_t* r, uint32_t saddr) {
    asm volatile(
        "ldmatrix.sync.aligned.m8n8.x4.trans.shared.b16 {%0,%1,%2,%3}, [%4];"
        : "=r"(r[0]), "=r"(r[1]), "=r"(r[2]), "=r"(r[3]) : "r"(saddr));
}

__device__ __forceinline__ void cpa16(uint32_t dst, const void* src) {
    asm volatile("cp.async.cg.shared.global [%0], [%1], 16;"
                 :: "r"(dst), "l"(src) : "memory");
}
#define CPA_COMMIT() asm volatile("cp.async.commit_group;" ::: "memory")
#define CPA_WAIT1()  asm volatile("cp.async.wait_group 1;" ::: "memory")
#define CPA_WAIT0()  asm volatile("cp.async.wait_group 0;" ::: "memory")

// ---------------- pre-convert fp32 -> fp16 ------------------------------------
__global__ void __launch_bounds__(256) cvt_inputs(
    const float* __restrict__ q, const float* __restrict__ k,
    const float* __restrict__ v)
{
    const float* src = (blockIdx.y == 0) ? q : (blockIdx.y == 1) ? k : v;
    __half* dst = (blockIdx.y == 0) ? g_qin : (blockIdx.y == 1) ? g_kin : g_vin;
    const int i = (blockIdx.x * 256 + threadIdx.x) * 4;
    float4 f = *(const float4*)&src[i];
    uint2 o;
    o.x = pack2h(f.x, f.y);
    o.y = pack2h(f.z, f.w);
    *(uint2*)&dst[i] = o;
}

__global__ void __launch_bounds__(256) cvt_weights(
    const float* __restrict__ wq, const float* __restrict__ wk,
    const float* __restrict__ wv, const float* __restrict__ wo)
{
    const float* src = (blockIdx.y == 0) ? wq : (blockIdx.y == 1) ? wk
                     : (blockIdx.y == 2) ? wv : wo;
    __half* dst = (blockIdx.y == 0) ? g_wqc : (blockIdx.y == 1) ? g_wkc
                : (blockIdx.y == 2) ? g_wvc : g_woc;
    const int i = (blockIdx.x * 256 + threadIdx.x) * 4;
    float4 f = *(const float4*)&src[i];
    uint2 o;
    o.x = pack2h(f.x, f.y);
    o.y = pack2h(f.z, f.w);
    *(uint2*)&dst[i] = o;
}

// ---------------- fp16 tensor GEMM: 3-stage cp.async pipeline -----------------
// C[4096,1024] = A @ W + bias. CTA 128x128, kt=32, 256 thr (8 warps 4m x 2n).
// mode 0: fp32 row-major out; mode 1: fp16 qh (*0.125); mode 3: fp16 natural.
__device__ __forceinline__ void gemm_fp16(
    const __half* __restrict__ A, const __half* __restrict__ W,
    const float* __restrict__ bias, void* __restrict__ outp,
    int mode, __half* As, __half* Bs)
{
    const int t    = threadIdx.x;
    const int lane = t & 31;
    const int w    = t >> 5;
    const int g    = lane >> 2;
    const int t4   = lane & 3;
    const int bm   = blockIdx.y * 128;
    const int bn   = blockIdx.x * 128;
    const int wm   = (w >> 1) * 32;
    const int wn   = (w & 1) * 64;

    int a_row[2], a_c8[2], b_row[2], b_c8[2];
#pragma unroll
    for (int r = 0; r < 2; ++r) {
        int lin = r * 256 + t;
        a_row[r] = lin >> 2;  a_c8[r] = (lin & 3) * 8;
        b_row[r] = lin >> 4;  b_c8[r] = (lin & 15) * 8;
    }

    const uint32_t as_b = (uint32_t)__cvta_generic_to_shared(As);
    const uint32_t bs_b = (uint32_t)__cvta_generic_to_shared(Bs);

    float acc[2][8][4];
#pragma unroll
    for (int mt = 0; mt < 2; ++mt)
#pragma unroll
        for (int nt = 0; nt < 8; ++nt)
#pragma unroll
            for (int i = 0; i < 4; ++i) acc[mt][nt][i] = 0.f;

#pragma unroll
    for (int s = 0; s < 2; ++s) {
        const int k0 = s * 32;
#pragma unroll
        for (int r = 0; r < 2; ++r) {
            cpa16(as_b + s * (ATILEH * 2) + (a_row[r] * ASTRH + a_c8[r]) * 2,
                  A + (size_t)(bm + a_row[r]) * 1024 + k0 + a_c8[r]);
            cpa16(bs_b + s * (BTILEH * 2) + (b_row[r] * BSTRH + b_c8[r]) * 2,
                  W + (size_t)(k0 + b_row[r]) * 1024 + bn + b_c8[r]);
        }
        CPA_COMMIT();
    }

    for (int it = 0; it < 32; ++it) {
        if (it < 30) { CPA_WAIT1(); } else { CPA_WAIT0(); }
        __syncthreads();
        const int stage = it % NST;
        const uint32_t abase = as_b + stage * (ATILEH * 2);
        const uint32_t bbase = bs_b + stage * (BTILEH * 2);
#pragma unroll
        for (int ks = 0; ks < 2; ++ks) {
            uint32_t af[2][4];
#pragma unroll
            for (int mt = 0; mt < 2; ++mt)
                ldsm4(af[mt], abase +
                      ((wm + mt * 16 + (lane & 15)) * ASTRH) * 2 +
                      (lane >> 4) * 16 + ks * 32);
#pragma unroll
            for (int dp = 0; dp < 4; ++dp) {
                uint32_t b[4];
                ldsm4t(b, bbase +
                       ((ks * 16 + (lane & 7) + (((lane >> 3) & 1) << 3)) * BSTRH) * 2 +
                       (lane >> 4) * 16 + (wn + dp * 16) * 2);
                mmah(acc[0][dp * 2],     af[0], b[0], b[1]);
                mmah(acc[0][dp * 2 + 1], af[0], b[2], b[3]);
                mmah(acc[1][dp * 2],     af[1], b[0], b[1]);
                mmah(acc[1][dp * 2 + 1], af[1], b[2], b[3]);
            }
        }
        if (it < 30) {
            const int s2 = (it + 2) % NST;
            const int k0 = (it + 2) * 32;
#pragma unroll
            for (int r = 0; r < 2; ++r) {
                cpa16(as_b + s2 * (ATILEH * 2) + (a_row[r] * ASTRH + a_c8[r]) * 2,
                      A + (size_t)(bm + a_row[r]) * 1024 + k0 + a_c8[r]);
                cpa16(bs_b + s2 * (BTILEH * 2) + (b_row[r] * BSTRH + b_c8[r]) * 2,
                      W + (size_t)(k0 + b_row[r]) * 1024 + bn + b_c8[r]);
            }
            CPA_COMMIT();
        }
    }

#pragma unroll
    for (int mt = 0; mt < 2; ++mt) {
        const int m0 = bm + wm + mt * 16 + g;
#pragma unroll
        for (int nt = 0; nt < 8; ++nt) {
            const int n0 = bn + wn + nt * 8 + 2 * t4;
            const float bz0 = bias[n0], bz1 = bias[n0 + 1];
            float v00 = acc[mt][nt][0] + bz0;
            float v01 = acc[mt][nt][1] + bz1;
            float v10 = acc[mt][nt][2] + bz0;
            float v11 = acc[mt][nt][3] + bz1;
            if (mode == 0) {
                float* out = (float*)outp;
                *(float2*)&out[(size_t)m0 * 1024 + n0]       = make_float2(v00, v01);
                *(float2*)&out[(size_t)(m0 + 8) * 1024 + n0] = make_float2(v10, v11);
            } else {
                __half* out = (__half*)outp;
                const int b0i = m0 >> 11, s0 = m0 & 2047;
                const int h = n0 >> 6, d = n0 & 63;
                const int bh = b0i * NHEAD + h;
                const float sc = (mode == 1) ? 0.125f : 1.0f;
                *(__half2*)&out[((size_t)bh * SEQ + s0) * DK + d] =
                    __floats2half2_rn(v00 * sc, v01 * sc);
                *(__half2*)&out[((size_t)bh * SEQ + s0 + 8) * DK + d] =
                    __floats2half2_rn(v10 * sc, v11 * sc);
            }
        }
    }
}

__global__ void __launch_bounds__(256, 2) qkv_gemm_p(
    const float* __restrict__ bq, const float* __restrict__ bk,
    const float* __restrict__ bv)
{
    extern __shared__ __half gsm[];
    __half* As = gsm;
    __half* Bs = gsm + NST * ATILEH;
    const int z = blockIdx.z;
    const __half* A      = (z == 0) ? g_qin : (z == 1) ? g_kin : g_vin;
    const __half* W      = (z == 0) ? g_wqc : (z == 1) ? g_wkc : g_wvc;
    const float*  bias   = (z == 0) ? bq    : (z == 1) ? bk    : bv;
    void* out            = (z == 0) ? (void*)g_qh : (z == 1) ? (void*)g_kh : (void*)g_vh;
    gemm_fp16(A, W, bias, out, (z == 0) ? 1 : 3, As, Bs);
}

__global__ void __launch_bounds__(256, 2) out_gemm(
    const float* __restrict__ bo, float* __restrict__ out)
{
    extern __shared__ __half gsm[];
    __half* As = gsm;
    __half* Bs = gsm + NST * ATILEH;
    gemm_fp16(g_ctx, g_woc, bo, out, 0, As, Bs);
}

// ---------------- attention: fp16 single-pass, fp16 u scratch -----------------
// 512 thr = 16 warps. warp = (mg = w>>2: 16 rows, kg = w&3: 32 keys/chunk).
__global__ void __launch_bounds__(512) attn_k(float* __restrict__ attn_out)
{
    extern __shared__ char smc[];
    __half* qs = (__half*)smc;               // 64*QSTRH halves = 9216 B
    __half* ks = qs + 64 * QSTRH;            // 2 bufs = 36864 B
    __half* vs = ks + 2 * 128 * KSTRH;       // 2 bufs = 36864 B
    float* stl = (float*)(vs + 2 * 128 * VSTRH);  // 256 floats
    float* fls = stl + 256;                       // 64 floats

    const int t    = threadIdx.x;
    const int lane = t & 31;
    const int w    = t >> 5;
    const int g    = lane >> 2;
    const int t4   = lane & 3;
    const int mg   = w >> 2;
    const int kg   = w & 3;
    const int bh   = blockIdx.y;
    const int q0   = blockIdx.x * QROWS;

    const uint32_t smem_b = (uint32_t)__cvta_generic_to_shared(smc);
    const uint32_t qs_b = smem_b;
    const uint32_t ks_b = smem_b + 64 * QSTRH * 2;
    const uint32_t vs_b = ks_b + 2 * KBUFB;

    const __half* kh  = g_kh + (size_t)bh * SEQ * DK;
    const __half* vh  = g_vh + (size_t)bh * SEQ * DK;

    int srow[2], scol8[2];
#pragma unroll
    for (int r = 0; r < 2; ++r) {
        int lin = r * 512 + t;
        srow[r] = lin >> 3;
        scol8[r] = (lin & 7) * 8;
    }

    {
        const __half* qb = g_qh + ((size_t)bh * SEQ + q0) * DK;
        const int r = t >> 3, c8 = (t & 7) * 8;
        *(uint4*)&qs[r * QSTRH + c8] = *(const uint4*)&qb[r * DK + c8];
    }
#pragma unroll
    for (int r = 0; r < 2; ++r) {
        cpa16(ks_b + (srow[r] * KSTRH + scol8[r]) * 2, kh + (size_t)srow[r] * DK + scol8[r]);
        cpa16(vs_b + (srow[r] * VSTRH + scol8[r]) * 2, vh + (size_t)srow[r] * DK + scol8[r]);
    }
    CPA_COMMIT();
    __syncthreads();

    uint32_t afr[4][4];
    {
        const uint32_t qlane = qs_b +
            ((mg * 16 + (lane & 15)) * QSTRH) * 2 + (lane >> 4) * 16;
#pragma unroll
        for (int db = 0; db < 4; ++db) ldsm4(afr[db], qlane + db * 32);
    }

    const uint32_t kfrag = ks_b +
        ((kg * 32 + (lane & 7) + ((lane >> 4) << 3)) * KSTRH) * 2 +
        ((lane >> 3) & 1) * 16;
    const uint32_t vfrag = vs_b +
        ((kg * 32 + (lane & 7) + (((lane >> 3) & 1) << 3)) * VSTRH) * 2 +
        (lane >> 4) * 16;

    float lrow[2] = {0.f, 0.f};
    float oacc[8][4];
#pragma unroll
    for (int nb = 0; nb < 8; ++nb)
#pragma unroll
        for (int i = 0; i < 4; ++i) oacc[nb][i] = 0.f;

    float*  attn_base = attn_out + ((size_t)bh * SEQ + q0) * SEQ;
    __half* us_base   = g_us + ((size_t)bh * SEQ + q0) * SEQ;

    for (int c = 0; c < NCH; ++c) {
        CPA_WAIT0();
        __syncthreads();
        if (c < NCH - 1) {
#pragma unroll
            for (int r = 0; r < 2; ++r) {
                cpa16(ks_b + ((c + 1) & 1) * KBUFB + (srow[r] * KSTRH + scol8[r]) * 2,
                      kh + ((size_t)(c + 1) * CHUNK + srow[r]) * DK + scol8[r]);
                cpa16(vs_b + ((c + 1) & 1) * VBUFB + (srow[r] * VSTRH + scol8[r]) * 2,
                      vh + ((size_t)(c + 1) * CHUNK + srow[r]) * DK + scol8[r]);
            }
            CPA_COMMIT();
        }

        const uint32_t kbb = kfrag + (c & 1) * KBUFB;
        float sacc[4][4];
#pragma unroll
        for (int nb = 0; nb < 4; ++nb)
#pragma unroll
            for (int i = 0; i < 4; ++i) sacc[nb][i] = 0.f;
#pragma unroll
        for (int db = 0; db < 4; ++db) {
#pragma unroll
            for (int pr = 0; pr < 2; ++pr) {
                uint32_t b[4];
                ldsm4(b, kbb + pr * (16 * KSTRH * 2) + db * 32);
                mmah(sacc[pr * 2],     afr[db], b[0], b[1]);
                mmah(sacc[pr * 2 + 1], afr[db], b[2], b[3]);
            }
        }

        // u = exp(s); row sums; packed fp16 u -> registers (PV A-frags) + g_us
        uint32_t pa[2][4];
        float csum0 = 0.f, csum1 = 0.f;
#pragma unroll
        for (int nb = 0; nb < 4; ++nb) {
            const float u00 = __expf(sacc[nb][0]);
            const float u01 = __expf(sacc[nb][1]);
            const float u10 = __expf(sacc[nb][2]);
            const float u11 = __expf(sacc[nb][3]);
            csum0 += u00 + u01;
            csum1 += u10 + u11;
            const uint32_t p0 = pack2h(u00, u01);
            const uint32_t p1 = pack2h(u10, u11);
            pa[nb >> 1][(nb & 1) * 2]     = p0;
            pa[nb >> 1][(nb & 1) * 2 + 1] = p1;
            const int col = c * CHUNK + kg * 32 + nb * 8 + 2 * t4;
            *(uint32_t*)&us_base[(size_t)(mg * 16 + g) * SEQ + col]     = p0;
            *(uint32_t*)&us_base[(size_t)(mg * 16 + g + 8) * SEQ + col] = p1;
        }
        csum0 += __shfl_xor_sync(~0u, csum0, 1);
        csum0 += __shfl_xor_sync(~0u, csum0, 2);
        csum1 += __shfl_xor_sync(~0u, csum1, 1);
        csum1 += __shfl_xor_sync(~0u, csum1, 2);
        lrow[0] += csum0;
        lrow[1] += csum1;

        const uint32_t vbb = vfrag + (c & 1) * VBUFB;
#pragma unroll
        for (int kb2 = 0; kb2 < 2; ++kb2) {
#pragma unroll
            for (int dp = 0; dp < 4; ++dp) {
                uint32_t b[4];
                ldsm4t(b, vbb + kb2 * (16 * VSTRH * 2) + dp * 32);
                mmah(oacc[dp * 2],     pa[kb2], b[0], b[1]);
                mmah(oacc[dp * 2 + 1], pa[kb2], b[2], b[3]);
            }
        }
    }

    // ---- l reduce across 4 key-group warps ----
    if (t4 == 0) {
        stl[kg * 64 + mg * 16 + g]     = lrow[0];
        stl[kg * 64 + mg * 16 + g + 8] = lrow[1];
    }
    __syncthreads();
    if (t < 64) {
        float fl = 0.f;
#pragma unroll
        for (int q = 0; q < 4; ++q) fl += stl[q * 64 + t];
        fls[t] = 1.0f / fl;
    }
    __syncthreads();

    // ---- fixup: read fp16 u (L2-resident), write normalized fp32 attn ----
#pragma unroll 4
    for (int i = t; i < 64 * 512; i += 512) {
        const int row = i >> 9;
        const int c4  = (i & 511) * 4;
        uint2 hv = *(const uint2*)&us_base[(size_t)row * SEQ + c4];
        __half2 h0 = *(__half2*)&hv.x;
        __half2 h1 = *(__half2*)&hv.y;
        float2 f0 = __half22float2(h0);
        float2 f1 = __half22float2(h1);
        const float s = fls[row];
        __stcs((float4*)&attn_base[(size_t)row * SEQ + c4],
               make_float4(f0.x * s, f0.y * s, f1.x * s, f1.y * s));
    }

    // ---- O reduce across 4 key-group warps per m-group (scale by 1/l) ----
    __syncthreads();
    float* osm = (float*)smc;   // 16 warps x [16][68]
#pragma unroll
    for (int nb = 0; nb < 8; ++nb) {
        const int oc = nb * 8 + 2 * t4;
        *(float2*)&osm[w * 1088 + g * 68 + oc]       = make_float2(oacc[nb][0], oacc[nb][1]);
        *(float2*)&osm[w * 1088 + (g + 8) * 68 + oc] = make_float2(oacc[nb][2], oacc[nb][3]);
    }
    __syncthreads();
    const int b = bh >> 4, h = bh & 15;
#pragma unroll
    for (int i = t; i < 4096; i += 512) {
        const int rr = i >> 6, d = i & 63;
        const int mg2 = rr >> 4, r16 = rr & 15;
        float s = 0.f;
#pragma unroll
        for (int q = 0; q < 4; ++q)
            s += osm[(mg2 * 4 + q) * 1088 + r16 * 68 + d];
        g_ctx[((size_t)b * SEQ + q0 + rr) * D_MODEL + h * DK + d] =
            __float2half(s * fls[rr]);
    }
}

// ---------------- launch -----------------------------------------------------
extern "C" void kernel_launch(void* const* d_in, const int* in_sizes, int n_in,
                              void* d_out, int out_size)
{
    (void)in_sizes; (void)n_in; (void)out_size;
    const float* q  = (const float*)d_in[0];
    const float* k  = (const float*)d_in[1];
    const float* v  = (const float*)d_in[2];
    const float* wq = (const float*)d_in[3];
    const float* bq = (const float*)d_in[4];
    const float* wk = (const float*)d_in[5];
    const float* bk = (const float*)d_in[6];
    const float* wv = (const float*)d_in[7];
    const float* bv = (const float*)d_in[8];
    const float* wo = (const float*)d_in[9];
    const float* bo = (const float*)d_in[10];

    float* out  = (float*)d_out;                       // [B,S,D]
    float* attn = out + (size_t)MROWS * D_MODEL;       // [B,H,S,S]

    const int asmem = 64 * QSTRH * 2 + 2 * KBUFB + 2 * VBUFB + (256 + 64) * 4; // 84224
    cudaFuncSetAttribute(attn_k, cudaFuncAttributeMaxDynamicSharedMemorySize, asmem);
    const int gsmem = NST * (ATILEH + BTILEH) * 2;   // 56832 B
    cudaFuncSetAttribute(qkv_gemm_p, cudaFuncAttributeMaxDynamicSharedMemorySize, gsmem);
    cudaFuncSetAttribute(out_gemm,   cudaFuncAttributeMaxDynamicSharedMemorySize, gsmem);

    cvt_inputs <<<dim3(MROWS * D_MODEL / (256 * 4), 3), 256>>>(q, k, v);
    cvt_weights<<<dim3(D_MODEL * D_MODEL / (256 * 4), 4), 256>>>(wq, wk, wv, wo);
    qkv_gemm_p<<<dim3(8, 32, 3), 256, gsmem>>>(bq, bk, bv);
    attn_k<<<dim3(SEQ / QROWS, NBH), 512, asmem>>>(attn);
    out_gemm<<<dim3(8, 32), 256, gsmem>>>(bo, out);
}

// round 16
// speedup vs baseline: 1.0379x; 1.0379x over previous
#include <cuda_runtime.h>
#include <cuda_fp16.h>
#include <cstdint>

#define D_MODEL 1024
#define NHEAD   16
#define DK      64
#define BB      2
#define SEQ     2048
#define MROWS   (BB * SEQ)   // 4096
#define NBH     (BB * NHEAD) // 32

// attention tiling: 32 q-rows per CTA, 256 threads, 2 CTAs/SM
#define QROWS 32
#define CHUNK 128
#define NCH   (SEQ / CHUNK)  // 16

// attention smem strides in HALVES
#define QSTRH 72
#define KSTRH 72
#define VSTRH 72
#define KBUFB (128 * KSTRH * 2)   // 18432 B
#define VBUFB (128 * VSTRH * 2)   // 18432 B

// fp16 GEMM strides (halves) / pipeline
#define ASTRH 40                  // A tile [128 m][32 k]
#define BSTRH 136                 // B tile [32 k][128 n]
#define NST   3
#define ATILEH (128 * ASTRH)      // 5120 halves
#define BTILEH (32 * BSTRH)       // 4352 halves

// ---------------- scratch (device globals) -----------------------------------
__device__ __half g_qin[MROWS * D_MODEL];
__device__ __half g_kin[MROWS * D_MODEL];
__device__ __half g_vin[MROWS * D_MODEL];
__device__ __half g_wqc[D_MODEL * D_MODEL];
__device__ __half g_wkc[D_MODEL * D_MODEL];
__device__ __half g_wvc[D_MODEL * D_MODEL];
__device__ __half g_woc[D_MODEL * D_MODEL];
__device__ __half g_qh [NBH * SEQ * DK];   // [bh][s][d] fp16, pre-scaled 1/8
__device__ __half g_kh [NBH * SEQ * DK];   // [bh][s][d] fp16
__device__ __half g_vh [NBH * SEQ * DK];   // [bh][s][d] fp16
__device__ __half g_ctx[MROWS * D_MODEL];  // [b*S+s][h*64+d] fp16

// ---------------- helpers ----------------------------------------------------
__device__ __forceinline__ uint32_t pack2h(float a, float b) {
    __half2 h = __floats2half2_rn(a, b);
    return *(uint32_t*)&h;
}

// fp16 m16n8k16
__device__ __forceinline__ void mmah(float* d, const uint32_t* a,
                                     uint32_t b0, uint32_t b1) {
    asm volatile(
        "mma.sync.aligned.m16n8k16.row.col.f32.f16.f16.f32 "
        "{%0,%1,%2,%3}, {%4,%5,%6,%7}, {%8,%9}, {%0,%1,%2,%3};"
        : "+f"(d[0]), "+f"(d[1]), "+f"(d[2]), "+f"(d[3])
        : "r"(a[0]), "r"(a[1]), "r"(a[2]), "r"(a[3]), "r"(b0), "r"(b1));
}

__device__ __forceinline__ void ldsm4(uint32_t* r, uint32_t saddr) {
    asm volatile(
        "ldmatrix.sync.aligned.m8n8.x4.shared.b16 {%0,%1,%2,%3}, [%4];"
        : "=r"(r[0]), "=r"(r[1]), "=r"(r[2]), "=r"(r[3]) : "r"(saddr));
}

__device__ __forceinline__ void ldsm4t(uint32_t* r, uint32_t saddr) {
    asm volatile(
        "ldmatrix.sync.aligned.m8n8.x4.trans.shared.b16 {%0,%1,%2,%3}, [%4];"
        : "=r"(r[0]), "=r"(r[1]), "=r"(r[2]), "=r"(r[3]) : "r"(saddr));
}

__device__ __forceinline__ void cpa16(uint32_t dst, const void* src) {
    asm volatile("cp.async.cg.shared.global [%0], [%1], 16;"
                 :: "r"(dst), "l"(src) : "memory");
}
#define CPA_COMMIT() asm volatile("cp.async.commit_group;" ::: "memory")
#define CPA_WAIT1()  asm volatile("cp.async.wait_group 1;" ::: "memory")
#define CPA_WAIT0()  asm volatile("cp.async.wait_group 0;" ::: "memory")

// ---------------- pre-convert fp32 -> fp16 ------------------------------------
__global__ void __launch_bounds__(256) cvt_inputs(
    const float* __restrict__ q, const float* __restrict__ k,
    const float* __restrict__ v)
{
    const float* src = (blockIdx.y == 0) ? q : (blockIdx.y == 1) ? k : v;
    __half* dst = (blockIdx.y == 0) ? g_qin : (blockIdx.y == 1) ? g_kin : g_vin;
    const int i = (blockIdx.x * 256 + threadIdx.x) * 4;
    float4 f = *(const float4*)&src[i];
    uint2 o;
    o.x = pack2h(f.x, f.y);
    o.y = pack2h(f.z, f.w);
    *(uint2*)&dst[i] = o;
}

__global__ void __launch_bounds__(256) cvt_weights(
    const float* __restrict__ wq, const float* __restrict__ wk,
    const float* __restrict__ wv, const float* __restrict__ wo)
{
    const float* src = (blockIdx.y == 0) ? wq : (blockIdx.y == 1) ? wk
                     : (blockIdx.y == 2) ? wv : wo;
    __half* dst = (blockIdx.y == 0) ? g_wqc : (blockIdx.y == 1) ? g_wkc
                : (blockIdx.y == 2) ? g_wvc : g_woc;
    const int i = (blockIdx.x * 256 + threadIdx.x) * 4;
    float4 f = *(const float4*)&src[i];
    uint2 o;
    o.x = pack2h(f.x, f.y);
    o.y = pack2h(f.z, f.w);
    *(uint2*)&dst[i] = o;
}

// ---------------- fp16 tensor GEMM: 3-stage cp.async pipeline (R14) -----------
__device__ __forceinline__ void gemm_fp16(
    const __half* __restrict__ A, const __half* __restrict__ W,
    const float* __restrict__ bias, void* __restrict__ outp,
    int mode, __half* As, __half* Bs)
{
    const int t    = threadIdx.x;
    const int lane = t & 31;
    const int w    = t >> 5;
    const int g    = lane >> 2;
    const int t4   = lane & 3;
    const int bm   = blockIdx.y * 128;
    const int bn   = blockIdx.x * 128;
    const int wm   = (w >> 1) * 32;
    const int wn   = (w & 1) * 64;

    int a_row[2], a_c8[2], b_row[2], b_c8[2];
#pragma unroll
    for (int r = 0; r < 2; ++r) {
        int lin = r * 256 + t;
        a_row[r] = lin >> 2;  a_c8[r] = (lin & 3) * 8;
        b_row[r] = lin >> 4;  b_c8[r] = (lin & 15) * 8;
    }

    const uint32_t as_b = (uint32_t)__cvta_generic_to_shared(As);
    const uint32_t bs_b = (uint32_t)__cvta_generic_to_shared(Bs);

    float acc[2][8][4];
#pragma unroll
    for (int mt = 0; mt < 2; ++mt)
#pragma unroll
        for (int nt = 0; nt < 8; ++nt)
#pragma unroll
            for (int i = 0; i < 4; ++i) acc[mt][nt][i] = 0.f;

#pragma unroll
    for (int s = 0; s < 2; ++s) {
        const int k0 = s * 32;
#pragma unroll
        for (int r = 0; r < 2; ++r) {
            cpa16(as_b + s * (ATILEH * 2) + (a_row[r] * ASTRH + a_c8[r]) * 2,
                  A + (size_t)(bm + a_row[r]) * 1024 + k0 + a_c8[r]);
            cpa16(bs_b + s * (BTILEH * 2) + (b_row[r] * BSTRH + b_c8[r]) * 2,
                  W + (size_t)(k0 + b_row[r]) * 1024 + bn + b_c8[r]);
        }
        CPA_COMMIT();
    }

    for (int it = 0; it < 32; ++it) {
        if (it < 30) { CPA_WAIT1(); } else { CPA_WAIT0(); }
        __syncthreads();
        const int stage = it % NST;
        const uint32_t abase = as_b + stage * (ATILEH * 2);
        const uint32_t bbase = bs_b + stage * (BTILEH * 2);
#pragma unroll
        for (int ks = 0; ks < 2; ++ks) {
            uint32_t af[2][4];
#pragma unroll
            for (int mt = 0; mt < 2; ++mt)
                ldsm4(af[mt], abase +
                      ((wm + mt * 16 + (lane & 15)) * ASTRH) * 2 +
                      (lane >> 4) * 16 + ks * 32);
#pragma unroll
            for (int dp = 0; dp < 4; ++dp) {
                uint32_t b[4];
                ldsm4t(b, bbase +
                       ((ks * 16 + (lane & 7) + (((lane >> 3) & 1) << 3)) * BSTRH) * 2 +
                       (lane >> 4) * 16 + (wn + dp * 16) * 2);
                mmah(acc[0][dp * 2],     af[0], b[0], b[1]);
                mmah(acc[0][dp * 2 + 1], af[0], b[2], b[3]);
                mmah(acc[1][dp * 2],     af[1], b[0], b[1]);
                mmah(acc[1][dp * 2 + 1], af[1], b[2], b[3]);
            }
        }
        if (it < 30) {
            const int s2 = (it + 2) % NST;
            const int k0 = (it + 2) * 32;
#pragma unroll
            for (int r = 0; r < 2; ++r) {
                cpa16(as_b + s2 * (ATILEH * 2) + (a_row[r] * ASTRH + a_c8[r]) * 2,
                      A + (size_t)(bm + a_row[r]) * 1024 + k0 + a_c8[r]);
                cpa16(bs_b + s2 * (BTILEH * 2) + (b_row[r] * BSTRH + b_c8[r]) * 2,
                      W + (size_t)(k0 + b_row[r]) * 1024 + bn + b_c8[r]);
            }
            CPA_COMMIT();
        }
    }

#pragma unroll
    for (int mt = 0; mt < 2; ++mt) {
        const int m0 = bm + wm + mt * 16 + g;
#pragma unroll
        for (int nt = 0; nt < 8; ++nt) {
            const int n0 = bn + wn + nt * 8 + 2 * t4;
            const float bz0 = bias[n0], bz1 = bias[n0 + 1];
            float v00 = acc[mt][nt][0] + bz0;
            float v01 = acc[mt][nt][1] + bz1;
            float v10 = acc[mt][nt][2] + bz0;
            float v11 = acc[mt][nt][3] + bz1;
            if (mode == 0) {
                float* out = (float*)outp;
                *(float2*)&out[(size_t)m0 * 1024 + n0]       = make_float2(v00, v01);
                *(float2*)&out[(size_t)(m0 + 8) * 1024 + n0] = make_float2(v10, v11);
            } else {
                __half* out = (__half*)outp;
                const int b0i = m0 >> 11, s0 = m0 & 2047;
                const int h = n0 >> 6, d = n0 & 63;
                const int bh = b0i * NHEAD + h;
                const float sc = (mode == 1) ? 0.125f : 1.0f;
                *(__half2*)&out[((size_t)bh * SEQ + s0) * DK + d] =
                    __floats2half2_rn(v00 * sc, v01 * sc);
                *(__half2*)&out[((size_t)bh * SEQ + s0 + 8) * DK + d] =
                    __floats2half2_rn(v10 * sc, v11 * sc);
            }
        }
    }
}

__global__ void __launch_bounds__(256, 2) qkv_gemm_p(
    const float* __restrict__ bq, const float* __restrict__ bk,
    const float* __restrict__ bv)
{
    extern __shared__ __half gsm[];
    __half* As = gsm;
    __half* Bs = gsm + NST * ATILEH;
    const int z = blockIdx.z;
    const __half* A      = (z == 0) ? g_qin : (z == 1) ? g_kin : g_vin;
    const __half* W      = (z == 0) ? g_wqc : (z == 1) ? g_wkc : g_wvc;
    const float*  bias   = (z == 0) ? bq    : (z == 1) ? bk    : bv;
    void* out            = (z == 0) ? (void*)g_qh : (z == 1) ? (void*)g_kh : (void*)g_vh;
    gemm_fp16(A, W, bias, out, (z == 0) ? 1 : 3, As, Bs);
}

__global__ void __launch_bounds__(256, 2) out_gemm(
    const float* __restrict__ bo, float* __restrict__ out)
{
    extern __shared__ __half gsm[];
    __half* As = gsm;
    __half* Bs = gsm + NST * ATILEH;
    gemm_fp16(g_ctx, g_woc, bo, out, 0, As, Bs);
}

// ---------------- attention: fp16, 32 q-rows, 256 thr, 2 CTAs/SM --------------
// 8 warps = 2 m-groups (16 rows) x 4 key-groups (32 keys/chunk).
// Double-buffered K/V; u fp32 in-place fixup (R14 scheme).
__global__ void __launch_bounds__(256, 2) attn_k(float* __restrict__ attn_out)
{
    extern __shared__ char smc[];
    __half* qs = (__half*)smc;               // 32*QSTRH halves = 4608 B
    __half* ks = qs + QROWS * QSTRH;         // 2 bufs = 36864 B
    __half* vs = ks + 2 * 128 * KSTRH;       // 2 bufs = 36864 B
    float* stl = (float*)(vs + 2 * 128 * VSTRH);  // 128 floats
    float* fls = stl + 128;                       // 32 floats

    const int t    = threadIdx.x;
    const int lane = t & 31;
    const int w    = t >> 5;       // 0..7
    const int g    = lane >> 2;
    const int t4   = lane & 3;
    const int mg   = w >> 2;       // 0..1 : rows mg*16..+15
    const int kg   = w & 3;        // 0..3 : keys kg*32..+31 within chunk
    const int bh   = blockIdx.y;
    const int q0   = blockIdx.x * QROWS;

    const uint32_t smem_b = (uint32_t)__cvta_generic_to_shared(smc);
    const uint32_t qs_b = smem_b;
    const uint32_t ks_b = smem_b + QROWS * QSTRH * 2;
    const uint32_t vs_b = ks_b + 2 * KBUFB;

    const __half* kh  = g_kh + (size_t)bh * SEQ * DK;
    const __half* vh  = g_vh + (size_t)bh * SEQ * DK;

    // cp.async indices: 4 x 16B per thread for each of K, V (128 rows x 128 B)
    int srow[4], scol8[4];
#pragma unroll
    for (int r = 0; r < 4; ++r) {
        int lin = r * 256 + t;
        srow[r] = lin >> 3;            // 0..127
        scol8[r] = (lin & 7) * 8;      // halves
    }

    // stage Q (32 rows x 64 d) + issue chunk-0 K/V loads
    {
        const __half* qb = g_qh + ((size_t)bh * SEQ + q0) * DK;
        const int r = t >> 3, c8 = (t & 7) * 8;
        *(uint4*)&qs[r * QSTRH + c8] = *(const uint4*)&qb[r * DK + c8];
    }
#pragma unroll
    for (int r = 0; r < 4; ++r) {
        cpa16(ks_b + (srow[r] * KSTRH + scol8[r]) * 2, kh + (size_t)srow[r] * DK + scol8[r]);
        cpa16(vs_b + (srow[r] * VSTRH + scol8[r]) * 2, vh + (size_t)srow[r] * DK + scol8[r]);
    }
    CPA_COMMIT();
    __syncthreads();

    // persistent Q A-fragments: 4 k16 blocks
    uint32_t afr[4][4];
    {
        const uint32_t qlane = qs_b +
            ((mg * 16 + (lane & 15)) * QSTRH) * 2 + (lane >> 4) * 16;
#pragma unroll
        for (int db = 0; db < 4; ++db) ldsm4(afr[db], qlane + db * 32);
    }

    const uint32_t kfrag = ks_b +
        ((kg * 32 + (lane & 7) + ((lane >> 4) << 3)) * KSTRH) * 2 +
        ((lane >> 3) & 1) * 16;
    const uint32_t vfrag = vs_b +
        ((kg * 32 + (lane & 7) + (((lane >> 3) & 1) << 3)) * VSTRH) * 2 +
        (lane >> 4) * 16;

    float lrow[2] = {0.f, 0.f};
    float oacc[8][4];
#pragma unroll
    for (int nb = 0; nb < 8; ++nb)
#pragma unroll
        for (int i = 0; i < 4; ++i) oacc[nb][i] = 0.f;

    float* attn_base = attn_out + ((size_t)bh * SEQ + q0) * SEQ;

    // ============== main loop: 1 barrier per chunk ==============
    for (int c = 0; c < NCH; ++c) {
        CPA_WAIT0();
        __syncthreads();
        if (c < NCH - 1) {
#pragma unroll
            for (int r = 0; r < 4; ++r) {
                cpa16(ks_b + ((c + 1) & 1) * KBUFB + (srow[r] * KSTRH + scol8[r]) * 2,
                      kh + ((size_t)(c + 1) * CHUNK + srow[r]) * DK + scol8[r]);
                cpa16(vs_b + ((c + 1) & 1) * VBUFB + (srow[r] * VSTRH + scol8[r]) * 2,
                      vh + ((size_t)(c + 1) * CHUNK + srow[r]) * DK + scol8[r]);
            }
            CPA_COMMIT();
        }

        // scores: 16 rows x 32 keys, K=64 (4 k16 blocks)
        const uint32_t kbb = kfrag + (c & 1) * KBUFB;
        float sacc[4][4];
#pragma unroll
        for (int nb = 0; nb < 4; ++nb)
#pragma unroll
            for (int i = 0; i < 4; ++i) sacc[nb][i] = 0.f;
#pragma unroll
        for (int db = 0; db < 4; ++db) {
#pragma unroll
            for (int pr = 0; pr < 2; ++pr) {
                uint32_t b[4];
                ldsm4(b, kbb + pr * (16 * KSTRH * 2) + db * 32);
                mmah(sacc[pr * 2],     afr[db], b[0], b[1]);
                mmah(sacc[pr * 2 + 1], afr[db], b[2], b[3]);
            }
        }

        // u = exp(s); row sums; P -> registers + fp32 u to gmem
        uint32_t pa[2][4];
        float csum0 = 0.f, csum1 = 0.f;
#pragma unroll
        for (int nb = 0; nb < 4; ++nb) {
            const float u00 = __expf(sacc[nb][0]);
            const float u01 = __expf(sacc[nb][1]);
            const float u10 = __expf(sacc[nb][2]);
            const float u11 = __expf(sacc[nb][3]);
            csum0 += u00 + u01;
            csum1 += u10 + u11;
            pa[nb >> 1][(nb & 1) * 2]     = pack2h(u00, u01);
            pa[nb >> 1][(nb & 1) * 2 + 1] = pack2h(u10, u11);
            const int col = c * CHUNK + kg * 32 + nb * 8 + 2 * t4;
            *(float2*)&attn_base[(size_t)(mg * 16 + g) * SEQ + col] =
                make_float2(u00, u01);
            *(float2*)&attn_base[(size_t)(mg * 16 + g + 8) * SEQ + col] =
                make_float2(u10, u11);
        }
        csum0 += __shfl_xor_sync(~0u, csum0, 1);
        csum0 += __shfl_xor_sync(~0u, csum0, 2);
        csum1 += __shfl_xor_sync(~0u, csum1, 1);
        csum1 += __shfl_xor_sync(~0u, csum1, 2);
        lrow[0] += csum0;
        lrow[1] += csum1;

        // P @ V: A = pa (registers), B = V via ldsm.trans
        const uint32_t vbb = vfrag + (c & 1) * VBUFB;
#pragma unroll
        for (int kb2 = 0; kb2 < 2; ++kb2) {
#pragma unroll
            for (int dp = 0; dp < 4; ++dp) {
                uint32_t b[4];
                ldsm4t(b, vbb + kb2 * (16 * VSTRH * 2) + dp * 32);
                mmah(oacc[dp * 2],     pa[kb2], b[0], b[1]);
                mmah(oacc[dp * 2 + 1], pa[kb2], b[2], b[3]);
            }
        }
    }

    // ---- l reduce across 4 key-group warps ----
    if (t4 == 0) {
        stl[kg * 32 + mg * 16 + g]     = lrow[0];
        stl[kg * 32 + mg * 16 + g + 8] = lrow[1];
    }
    __syncthreads();
    if (t < 32) {
        float fl = 0.f;
#pragma unroll
        for (int q = 0; q < 4; ++q) fl += stl[q * 32 + t];
        fls[t] = 1.0f / fl;
    }
    __syncthreads();

    // ---- in-place fixup: scale u by 1/l (float4, L2-resident) ----
#pragma unroll 4
    for (int i = t; i < QROWS * 512; i += 256) {
        const int row = i >> 9;
        const int c4  = (i & 511) * 4;
        float4 v = __ldcg((const float4*)&attn_base[(size_t)row * SEQ + c4]);
        const float s = fls[row];
        v.x *= s; v.y *= s; v.z *= s; v.w *= s;
        __stcs((float4*)&attn_base[(size_t)row * SEQ + c4], v);
    }

    // ---- O reduce across 4 key-group warps per m-group (scale by 1/l) ----
    __syncthreads();
    float* osm = (float*)smc;   // 8 warps x [16][68] = 34816 B (below stl)
#pragma unroll
    for (int nb = 0; nb < 8; ++nb) {
        const int oc = nb * 8 + 2 * t4;
        *(float2*)&osm[w * 1088 + g * 68 + oc]       = make_float2(oacc[nb][0], oacc[nb][1]);
        *(float2*)&osm[w * 1088 + (g + 8) * 68 + oc] = make_float2(oacc[nb][2], oacc[nb][3]);
    }
    __syncthreads();
    const int b = bh >> 4, h = bh & 15;
#pragma unroll
    for (int i = t; i < QROWS * 64; i += 256) {
        const int rr = i >> 6, d = i & 63;
        const int mg2 = rr >> 4, r16 = rr & 15;
        float s = 0.f;
#pragma unroll
        for (int q = 0; q < 4; ++q)
            s += osm[(mg2 * 4 + q) * 1088 + r16 * 68 + d];
        g_ctx[((size_t)b * SEQ + q0 + rr) * D_MODEL + h * DK + d] =
            __float2half(s * fls[rr]);
    }
}

// ---------------- launch -----------------------------------------------------
extern "C" void kernel_launch(void* const* d_in, const int* in_sizes, int n_in,
                              void* d_out, int out_size)
{
    (void)in_sizes; (void)n_in; (void)out_size;
    const float* q  = (const float*)d_in[0];
    const float* k  = (const float*)d_in[1];
    const float* v  = (const float*)d_in[2];
    const float* wq = (const float*)d_in[3];
    const float* bq = (const float*)d_in[4];
    const float* wk = (const float*)d_in[5];
    const float* bk = (const float*)d_in[6];
    const float* wv = (const float*)d_in[7];
    const float* bv = (const float*)d_in[8];
    const float* wo = (const float*)d_in[9];
    const float* bo = (const float*)d_in[10];

    float* out  = (float*)d_out;                       // [B,S,D]
    float* attn = out + (size_t)MROWS * D_MODEL;       // [B,H,S,S]

    const int asmem = QROWS * QSTRH * 2 + 2 * KBUFB + 2 * VBUFB + (128 + 32) * 4; // 78976
    cudaFuncSetAttribute(attn_k, cudaFuncAttributeMaxDynamicSharedMemorySize, asmem);
    const int gsmem = NST * (ATILEH + BTILEH) * 2;   // 56832 B
    cudaFuncSetAttribute(qkv_gemm_p, cudaFuncAttributeMaxDynamicSharedMemorySize, gsmem);
    cudaFuncSetAttribute(out_gemm,   cudaFuncAttributeMaxDynamicSharedMemorySize, gsmem);

    cvt_inputs <<<dim3(MROWS * D_MODEL / (256 * 4), 3), 256>>>(q, k, v);
    cvt_weights<<<dim3(D_MODEL * D_MODEL / (256 * 4), 4), 256>>>(wq, wk, wv, wo);
    qkv_gemm_p<<<dim3(8, 32, 3), 256, gsmem>>>(bq, bk, bv);
    attn_k<<<dim3(SEQ / QROWS, NBH), 256, asmem>>>(attn);
    out_gemm<<<dim3(8, 32), 256, gsmem>>>(bo, out);
}

// round 17
// speedup vs baseline: 1.0605x; 1.0218x over previous
#include <cuda_runtime.h>
#include <cuda_fp16.h>
#include <cstdint>

#define D_MODEL 1024
#define NHEAD   16
#define DK      64
#define BB      2
#define SEQ     2048
#define MROWS   (BB * SEQ)   // 4096
#define NBH     (BB * NHEAD) // 32

// attention tiling (R14 shape)
#define QROWS 64
#define CHUNK 128
#define NCH   (SEQ / CHUNK)  // 16
#define NBUF  3              // chunk pipeline depth

// attention smem strides in HALVES
#define QSTRH 72
#define KSTRH 72
#define VSTRH 72
#define KBUFB (128 * KSTRH * 2)   // 18432 B
#define VBUFB (128 * VSTRH * 2)   // 18432 B

// fp16 GEMM strides (halves) / pipeline
#define ASTRH 40                  // A tile [128 m][32 k]
#define BSTRH 136                 // B tile [32 k][128 n]
#define NST   3
#define ATILEH (128 * ASTRH)      // 5120 halves
#define BTILEH (32 * BSTRH)       // 4352 halves

// ---------------- scratch (device globals) -----------------------------------
__device__ __half g_qin[MROWS * D_MODEL];
__device__ __half g_kin[MROWS * D_MODEL];
__device__ __half g_vin[MROWS * D_MODEL];
__device__ __half g_wqc[D_MODEL * D_MODEL];
__device__ __half g_wkc[D_MODEL * D_MODEL];
__device__ __half g_wvc[D_MODEL * D_MODEL];
__device__ __half g_woc[D_MODEL * D_MODEL];
__device__ __half g_qh [NBH * SEQ * DK];   // [bh][s][d] fp16, pre-scaled 1/8
__device__ __half g_kh [NBH * SEQ * DK];   // [bh][s][d] fp16
__device__ __half g_vh [NBH * SEQ * DK];   // [bh][s][d] fp16
__device__ __half g_ctx[MROWS * D_MODEL];  // [b*S+s][h*64+d] fp16

// ---------------- helpers ----------------------------------------------------
__device__ __forceinline__ uint32_t pack2h(float a, float b) {
    __half2 h = __floats2half2_rn(a, b);
    return *(uint32_t*)&h;
}

// fp16 m16n8k16
__device__ __forceinline__ void mmah(float* d, const uint32_t* a,
                                     uint32_t b0, uint32_t b1) {
    asm volatile(
        "mma.sync.aligned.m16n8k16.row.col.f32.f16.f16.f32 "
        "{%0,%1,%2,%3}, {%4,%5,%6,%7}, {%8,%9}, {%0,%1,%2,%3};"
        : "+f"(d[0]), "+f"(d[1]), "+f"(d[2]), "+f"(d[3])
        : "r"(a[0]), "r"(a[1]), "r"(a[2]), "r"(a[3]), "r"(b0), "r"(b1));
}

__device__ __forceinline__ void ldsm4(uint32_t* r, uint32_t saddr) {
    asm volatile(
        "ldmatrix.sync.aligned.m8n8.x4.shared.b16 {%0,%1,%2,%3}, [%4];"
        : "=r"(r[0]), "=r"(r[1]), "=r"(r[2]), "=r"(r[3]) : "r"(saddr));
}

__device__ __forceinline__ void ldsm4t(uint32_t* r, uint32_t saddr) {
    asm volatile(
        "ldmatrix.sync.aligned.m8n8.x4.trans.shared.b16 {%0,%1,%2,%3}, [%4];"
        : "=r"(r[0]), "=r"(r[1]), "=r"(r[2]), "=r"(r[3]) : "r"(saddr));
}

__device__ __forceinline__ void cpa16(uint32_t dst, const void* src) {
    asm volatile("cp.async.cg.shared.global [%0], [%1], 16;"
                 :: "r"(dst), "l"(src) : "memory");
}
#define CPA_COMMIT() asm volatile("cp.async.commit_group;" ::: "memory")
#define CPA_WAIT1()  asm volatile("cp.async.wait_group 1;" ::: "memory")
#define CPA_WAIT0()  asm volatile("cp.async.wait_group 0;" ::: "memory")

// ---------------- pre-convert fp32 -> fp16 ------------------------------------
__global__ void __launch_bounds__(256) cvt_inputs(
    const float* __restrict__ q, const float* __restrict__ k,
    const float* __restrict__ v)
{
    const float* src = (blockIdx.y == 0) ? q : (blockIdx.y == 1) ? k : v;
    __half* dst = (blockIdx.y == 0) ? g_qin : (blockIdx.y == 1) ? g_kin : g_vin;
    const int i = (blockIdx.x * 256 + threadIdx.x) * 4;
    float4 f = *(const float4*)&src[i];
    uint2 o;
    o.x = pack2h(f.x, f.y);
    o.y = pack2h(f.z, f.w);
    *(uint2*)&dst[i] = o;
}

__global__ void __launch_bounds__(256) cvt_weights(
    const float* __restrict__ wq, const float* __restrict__ wk,
    const float* __restrict__ wv, const float* __restrict__ wo)
{
    const float* src = (blockIdx.y == 0) ? wq : (blockIdx.y == 1) ? wk
                     : (blockIdx.y == 2) ? wv : wo;
    __half* dst = (blockIdx.y == 0) ? g_wqc : (blockIdx.y == 1) ? g_wkc
                : (blockIdx.y == 2) ? g_wvc : g_woc;
    const int i = (blockIdx.x * 256 + threadIdx.x) * 4;
    float4 f = *(const float4*)&src[i];
    uint2 o;
    o.x = pack2h(f.x, f.y);
    o.y = pack2h(f.z, f.w);
    *(uint2*)&dst[i] = o;
}

// ---------------- fp16 tensor GEMM: 3-stage cp.async pipeline (R14) -----------
__device__ __forceinline__ void gemm_fp16(
    const __half* __restrict__ A, const __half* __restrict__ W,
    const float* __restrict__ bias, void* __restrict__ outp,
    int mode, __half* As, __half* Bs)
{
    const int t    = threadIdx.x;
    const int lane = t & 31;
    const int w    = t >> 5;
    const int g    = lane >> 2;
    const int t4   = lane & 3;
    const int bm   = blockIdx.y * 128;
    const int bn   = blockIdx.x * 128;
    const int wm   = (w >> 1) * 32;
    const int wn   = (w & 1) * 64;

    int a_row[2], a_c8[2], b_row[2], b_c8[2];
#pragma unroll
    for (int r = 0; r < 2; ++r) {
        int lin = r * 256 + t;
        a_row[r] = lin >> 2;  a_c8[r] = (lin & 3) * 8;
        b_row[r] = lin >> 4;  b_c8[r] = (lin & 15) * 8;
    }

    const uint32_t as_b = (uint32_t)__cvta_generic_to_shared(As);
    const uint32_t bs_b = (uint32_t)__cvta_generic_to_shared(Bs);

    float acc[2][8][4];
#pragma unroll
    for (int mt = 0; mt < 2; ++mt)
#pragma unroll
        for (int nt = 0; nt < 8; ++nt)
#pragma unroll
            for (int i = 0; i < 4; ++i) acc[mt][nt][i] = 0.f;

#pragma unroll
    for (int s = 0; s < 2; ++s) {
        const int k0 = s * 32;
#pragma unroll
        for (int r = 0; r < 2; ++r) {
            cpa16(as_b + s * (ATILEH * 2) + (a_row[r] * ASTRH + a_c8[r]) * 2,
                  A + (size_t)(bm + a_row[r]) * 1024 + k0 + a_c8[r]);
            cpa16(bs_b + s * (BTILEH * 2) + (b_row[r] * BSTRH + b_c8[r]) * 2,
                  W + (size_t)(k0 + b_row[r]) * 1024 + bn + b_c8[r]);
        }
        CPA_COMMIT();
    }

    for (int it = 0; it < 32; ++it) {
        if (it < 30) { CPA_WAIT1(); } else { CPA_WAIT0(); }
        __syncthreads();
        const int stage = it % NST;
        const uint32_t abase = as_b + stage * (ATILEH * 2);
        const uint32_t bbase = bs_b + stage * (BTILEH * 2);
#pragma unroll
        for (int ks = 0; ks < 2; ++ks) {
            uint32_t af[2][4];
#pragma unroll
            for (int mt = 0; mt < 2; ++mt)
                ldsm4(af[mt], abase +
                      ((wm + mt * 16 + (lane & 15)) * ASTRH) * 2 +
                      (lane >> 4) * 16 + ks * 32);
#pragma unroll
            for (int dp = 0; dp < 4; ++dp) {
                uint32_t b[4];
                ldsm4t(b, bbase +
                       ((ks * 16 + (lane & 7) + (((lane >> 3) & 1) << 3)) * BSTRH) * 2 +
                       (lane >> 4) * 16 + (wn + dp * 16) * 2);
                mmah(acc[0][dp * 2],     af[0], b[0], b[1]);
                mmah(acc[0][dp * 2 + 1], af[0], b[2], b[3]);
                mmah(acc[1][dp * 2],     af[1], b[0], b[1]);
                mmah(acc[1][dp * 2 + 1], af[1], b[2], b[3]);
            }
        }
        if (it < 30) {
            const int s2 = (it + 2) % NST;
            const int k0 = (it + 2) * 32;
#pragma unroll
            for (int r = 0; r < 2; ++r) {
                cpa16(as_b + s2 * (ATILEH * 2) + (a_row[r] * ASTRH + a_c8[r]) * 2,
                      A + (size_t)(bm + a_row[r]) * 1024 + k0 + a_c8[r]);
                cpa16(bs_b + s2 * (BTILEH * 2) + (b_row[r] * BSTRH + b_c8[r]) * 2,
                      W + (size_t)(k0 + b_row[r]) * 1024 + bn + b_c8[r]);
            }
            CPA_COMMIT();
        }
    }

#pragma unroll
    for (int mt = 0; mt < 2; ++mt) {
        const int m0 = bm + wm + mt * 16 + g;
#pragma unroll
        for (int nt = 0; nt < 8; ++nt) {
            const int n0 = bn + wn + nt * 8 + 2 * t4;
            const float bz0 = bias[n0], bz1 = bias[n0 + 1];
            float v00 = acc[mt][nt][0] + bz0;
            float v01 = acc[mt][nt][1] + bz1;
            float v10 = acc[mt][nt][2] + bz0;
            float v11 = acc[mt][nt][3] + bz1;
            if (mode == 0) {
                float* out = (float*)outp;
                *(float2*)&out[(size_t)m0 * 1024 + n0]       = make_float2(v00, v01);
                *(float2*)&out[(size_t)(m0 + 8) * 1024 + n0] = make_float2(v10, v11);
            } else {
                __half* out = (__half*)outp;
                const int b0i = m0 >> 11, s0 = m0 & 2047;
                const int h = n0 >> 6, d = n0 & 63;
                const int bh = b0i * NHEAD + h;
                const float sc = (mode == 1) ? 0.125f : 1.0f;
                *(__half2*)&out[((size_t)bh * SEQ + s0) * DK + d] =
                    __floats2half2_rn(v00 * sc, v01 * sc);
                *(__half2*)&out[((size_t)bh * SEQ + s0 + 8) * DK + d] =
                    __floats2half2_rn(v10 * sc, v11 * sc);
            }
        }
    }
}

__global__ void __launch_bounds__(256, 2) qkv_gemm_p(
    const float* __restrict__ bq, const float* __restrict__ bk,
    const float* __restrict__ bv)
{
    extern __shared__ __half gsm[];
    __half* As = gsm;
    __half* Bs = gsm + NST * ATILEH;
    const int z = blockIdx.z;
    const __half* A      = (z == 0) ? g_qin : (z == 1) ? g_kin : g_vin;
    const __half* W      = (z == 0) ? g_wqc : (z == 1) ? g_wkc : g_wvc;
    const float*  bias   = (z == 0) ? bq    : (z == 1) ? bk    : bv;
    void* out            = (z == 0) ? (void*)g_qh : (z == 1) ? (void*)g_kh : (void*)g_vh;
    gemm_fp16(A, W, bias, out, (z == 0) ? 1 : 3, As, Bs);
}

__global__ void __launch_bounds__(256, 2) out_gemm(
    const float* __restrict__ bo, float* __restrict__ out)
{
    extern __shared__ __half gsm[];
    __half* As = gsm;
    __half* Bs = gsm + NST * ATILEH;
    gemm_fp16(g_ctx, g_woc, bo, out, 0, As, Bs);
}

// ---------------- attention: fp16 single-pass, 3-deep chunk pipeline ----------
// 512 thr = 16 warps. warp = (mg = w>>2: 16 rows, kg = w&3: 32 keys/chunk).
// u = exp(s) unnormalized; in-place L2 fixup scales by 1/l at the end.
__global__ void __launch_bounds__(512) attn_k(float* __restrict__ attn_out)
{
    extern __shared__ char smc[];
    __half* qs = (__half*)smc;               // 64*QSTRH halves = 9216 B
    __half* ks = qs + 64 * QSTRH;            // NBUF bufs = 55296 B
    __half* vs = ks + NBUF * 128 * KSTRH;    // NBUF bufs = 55296 B
    float* stl = (float*)(vs + NBUF * 128 * VSTRH);  // 256 floats
    float* fls = stl + 256;                          // 64 floats

    const int t    = threadIdx.x;
    const int lane = t & 31;
    const int w    = t >> 5;
    const int g    = lane >> 2;
    const int t4   = lane & 3;
    const int mg   = w >> 2;
    const int kg   = w & 3;
    const int bh   = blockIdx.y;
    const int q0   = blockIdx.x * QROWS;

    const uint32_t smem_b = (uint32_t)__cvta_generic_to_shared(smc);
    const uint32_t qs_b = smem_b;
    const uint32_t ks_b = smem_b + 64 * QSTRH * 2;
    const uint32_t vs_b = ks_b + NBUF * KBUFB;

    const __half* kh  = g_kh + (size_t)bh * SEQ * DK;
    const __half* vh  = g_vh + (size_t)bh * SEQ * DK;

    int srow[2], scol8[2];
#pragma unroll
    for (int r = 0; r < 2; ++r) {
        int lin = r * 512 + t;
        srow[r] = lin >> 3;
        scol8[r] = (lin & 7) * 8;
    }

    // stage Q; issue chunks 0 and 1 (one commit group per chunk)
    {
        const __half* qb = g_qh + ((size_t)bh * SEQ + q0) * DK;
        const int r = t >> 3, c8 = (t & 7) * 8;
        *(uint4*)&qs[r * QSTRH + c8] = *(const uint4*)&qb[r * DK + c8];
    }
#pragma unroll
    for (int s = 0; s < 2; ++s) {
#pragma unroll
        for (int r = 0; r < 2; ++r) {
            cpa16(ks_b + s * KBUFB + (srow[r] * KSTRH + scol8[r]) * 2,
                  kh + ((size_t)s * CHUNK + srow[r]) * DK + scol8[r]);
            cpa16(vs_b + s * VBUFB + (srow[r] * VSTRH + scol8[r]) * 2,
                  vh + ((size_t)s * CHUNK + srow[r]) * DK + scol8[r]);
        }
        CPA_COMMIT();
    }
    __syncthreads();   // qs visible

    // persistent Q A-fragments: 4 k16 blocks
    uint32_t afr[4][4];
    {
        const uint32_t qlane = qs_b +
            ((mg * 16 + (lane & 15)) * QSTRH) * 2 + (lane >> 4) * 16;
#pragma unroll
        for (int db = 0; db < 4; ++db) ldsm4(afr[db], qlane + db * 32);
    }

    const uint32_t kfrag = ks_b +
        ((kg * 32 + (lane & 7) + ((lane >> 4) << 3)) * KSTRH) * 2 +
        ((lane >> 3) & 1) * 16;
    const uint32_t vfrag = vs_b +
        ((kg * 32 + (lane & 7) + (((lane >> 3) & 1) << 3)) * VSTRH) * 2 +
        (lane >> 4) * 16;

    float lrow[2] = {0.f, 0.f};
    float oacc[8][4];
#pragma unroll
    for (int nb = 0; nb < 8; ++nb)
#pragma unroll
        for (int i = 0; i < 4; ++i) oacc[nb][i] = 0.f;

    float* attn_base = attn_out + ((size_t)bh * SEQ + q0) * SEQ;

    // ============== main loop: lookahead 2, 1 barrier per chunk ==============
    for (int c = 0; c < NCH; ++c) {
        if (c < NCH - 1) { CPA_WAIT1(); } else { CPA_WAIT0(); }
        __syncthreads();   // chunk c visible everywhere; compute(c-1) done
        if (c < NCH - 2) { // issue chunk c+2 into buffer freed by compute(c-1)
            const int s2 = (c + 2) % NBUF;
#pragma unroll
            for (int r = 0; r < 2; ++r) {
                cpa16(ks_b + s2 * KBUFB + (srow[r] * KSTRH + scol8[r]) * 2,
                      kh + ((size_t)(c + 2) * CHUNK + srow[r]) * DK + scol8[r]);
                cpa16(vs_b + s2 * VBUFB + (srow[r] * VSTRH + scol8[r]) * 2,
                      vh + ((size_t)(c + 2) * CHUNK + srow[r]) * DK + scol8[r]);
            }
            CPA_COMMIT();
        }

        // scores: 16 rows x 32 keys, K=64 (4 k16 blocks)
        const uint32_t kbb = kfrag + (c % NBUF) * KBUFB;
        float sacc[4][4];
#pragma unroll
        for (int nb = 0; nb < 4; ++nb)
#pragma unroll
            for (int i = 0; i < 4; ++i) sacc[nb][i] = 0.f;
#pragma unroll
        for (int db = 0; db < 4; ++db) {
#pragma unroll
            for (int pr = 0; pr < 2; ++pr) {
                uint32_t b[4];
                ldsm4(b, kbb + pr * (16 * KSTRH * 2) + db * 32);
                mmah(sacc[pr * 2],     afr[db], b[0], b[1]);
                mmah(sacc[pr * 2 + 1], afr[db], b[2], b[3]);
            }
        }

        // u = exp(s); row sums; P -> registers + fp32 u to gmem
        uint32_t pa[2][4];
        float csum0 = 0.f, csum1 = 0.f;
#pragma unroll
        for (int nb = 0; nb < 4; ++nb) {
            const float u00 = __expf(sacc[nb][0]);
            const float u01 = __expf(sacc[nb][1]);
            const float u10 = __expf(sacc[nb][2]);
            const float u11 = __expf(sacc[nb][3]);
            csum0 += u00 + u01;
            csum1 += u10 + u11;
            pa[nb >> 1][(nb & 1) * 2]     = pack2h(u00, u01);
            pa[nb >> 1][(nb & 1) * 2 + 1] = pack2h(u10, u11);
            const int col = c * CHUNK + kg * 32 + nb * 8 + 2 * t4;
            *(float2*)&attn_base[(size_t)(mg * 16 + g) * SEQ + col] =
                make_float2(u00, u01);
            *(float2*)&attn_base[(size_t)(mg * 16 + g + 8) * SEQ + col] =
                make_float2(u10, u11);
        }
        csum0 += __shfl_xor_sync(~0u, csum0, 1);
        csum0 += __shfl_xor_sync(~0u, csum0, 2);
        csum1 += __shfl_xor_sync(~0u, csum1, 1);
        csum1 += __shfl_xor_sync(~0u, csum1, 2);
        lrow[0] += csum0;
        lrow[1] += csum1;

        // P @ V: A = pa (registers), B = V via ldsm.trans
        const uint32_t vbb = vfrag + (c % NBUF) * VBUFB;
#pragma unroll
        for (int kb2 = 0; kb2 < 2; ++kb2) {
#pragma unroll
            for (int dp = 0; dp < 4; ++dp) {
                uint32_t b[4];
                ldsm4t(b, vbb + kb2 * (16 * VSTRH * 2) + dp * 32);
                mmah(oacc[dp * 2],     pa[kb2], b[0], b[1]);
                mmah(oacc[dp * 2 + 1], pa[kb2], b[2], b[3]);
            }
        }
    }

    // ---- l reduce across 4 key-group warps ----
    if (t4 == 0) {
        stl[kg * 64 + mg * 16 + g]     = lrow[0];
        stl[kg * 64 + mg * 16 + g + 8] = lrow[1];
    }
    __syncthreads();
    if (t < 64) {
        float fl = 0.f;
#pragma unroll
        for (int q = 0; q < 4; ++q) fl += stl[q * 64 + t];
        fls[t] = 1.0f / fl;
    }
    __syncthreads();

    // ---- in-place fixup: scale u by 1/l (float4, L2-resident) ----
#pragma unroll 4
    for (int i = t; i < 64 * 512; i += 512) {
        const int row = i >> 9;
        const int c4  = (i & 511) * 4;
        float4 v = __ldcg((const float4*)&attn_base[(size_t)row * SEQ + c4]);
        const float s = fls[row];
        v.x *= s; v.y *= s; v.z *= s; v.w *= s;
        __stcs((float4*)&attn_base[(size_t)row * SEQ + c4], v);
    }

    // ---- O reduce across 4 key-group warps per m-group (scale by 1/l) ----
    __syncthreads();
    float* osm = (float*)smc;   // 16 warps x [16][68]
#pragma unroll
    for (int nb = 0; nb < 8; ++nb) {
        const int oc = nb * 8 + 2 * t4;
        *(float2*)&osm[w * 1088 + g * 68 + oc]       = make_float2(oacc[nb][0], oacc[nb][1]);
        *(float2*)&osm[w * 1088 + (g + 8) * 68 + oc] = make_float2(oacc[nb][2], oacc[nb][3]);
    }
    __syncthreads();
    const int b = bh >> 4, h = bh & 15;
#pragma unroll
    for (int i = t; i < 4096; i += 512) {
        const int rr = i >> 6, d = i & 63;
        const int mg2 = rr >> 4, r16 = rr & 15;
        float s = 0.f;
#pragma unroll
        for (int q = 0; q < 4; ++q)
            s += osm[(mg2 * 4 + q) * 1088 + r16 * 68 + d];
        g_ctx[((size_t)b * SEQ + q0 + rr) * D_MODEL + h * DK + d] =
            __float2half(s * fls[rr]);
    }
}

// ---------------- launch -----------------------------------------------------
extern "C" void kernel_launch(void* const* d_in, const int* in_sizes, int n_in,
                              void* d_out, int out_size)
{
    (void)in_sizes; (void)n_in; (void)out_size;
    const float* q  = (const float*)d_in[0];
    const float* k  = (const float*)d_in[1];
    const float* v  = (const float*)d_in[2];
    const float* wq = (const float*)d_in[3];
    const float* bq = (const float*)d_in[4];
    const float* wk = (const float*)d_in[5];
    const float* bk = (const float*)d_in[6];
    const float* wv = (const float*)d_in[7];
    const float* bv = (const float*)d_in[8];
    const float* wo = (const float*)d_in[9];
    const float* bo = (const float*)d_in[10];

    float* out  = (float*)d_out;                       // [B,S,D]
    float* attn = out + (size_t)MROWS * D_MODEL;       // [B,H,S,S]

    const int asmem = 64 * QSTRH * 2 + NBUF * (KBUFB + VBUFB) + (256 + 64) * 4; // 121088
    cudaFuncSetAttribute(attn_k, cudaFuncAttributeMaxDynamicSharedMemorySize, asmem);
    const int gsmem = NST * (ATILEH + BTILEH) * 2;   // 56832 B
    cudaFuncSetAttribute(qkv_gemm_p, cudaFuncAttributeMaxDynamicSharedMemorySize, gsmem);
    cudaFuncSetAttribute(out_gemm,   cudaFuncAttributeMaxDynamicSharedMemorySize, gsmem);

    cvt_inputs <<<dim3(MROWS * D_MODEL / (256 * 4), 3), 256>>>(q, k, v);
    cvt_weights<<<dim3(D_MODEL * D_MODEL / (256 * 4), 4), 256>>>(wq, wk, wv, wo);
    qkv_gemm_p<<<dim3(8, 32, 3), 256, gsmem>>>(bq, bk, bv);
    attn_k<<<dim3(SEQ / QROWS, NBH), 512, asmem>>>(attn);
    out_gemm<<<dim3(8, 32), 256, gsmem>>>(bo, out);
}